// round 1
// baseline (speedup 1.0000x reference)
#include <cuda_runtime.h>
#include <cstddef>

#define LSEQ 256
#define NB   8
#define NC   64
#define TRI  (LSEQ * (LSEQ - 1) / 2)   // 32640 upper-triangle cells (w >= 1)

// Scratch for t = max_c scores, stored in packed-diagonal layout per batch:
// g_td[b*TRI + off1(w) + i] = max_c scores[b, i, i+w, c]
__device__ float g_td[NB * TRI];

// off1(w) = sum_{v=1}^{w-1} (LSEQ - v)
__host__ __device__ __forceinline__ int off1(int w) {
    return (w - 1) * LSEQ - ((w - 1) * w) / 2;
}

// ---------------------------------------------------------------------------
// Kernel 1: t[b,i,e] = max over C of scores[b,i,e,:], upper triangle only.
// One warp per cell; lanes read c=lane and c=lane+32 (two coalesced 128B
// transactions), then butterfly max-reduce. Grid: (LSEQ-1 rows, NB batches).
// ---------------------------------------------------------------------------
__global__ void max_kernel(const float* __restrict__ scores) {
    const int i    = blockIdx.x;          // 0 .. LSEQ-2
    const int b    = blockIdx.y;
    const int warp = threadIdx.x >> 5;    // 0..7
    const int lane = threadIdx.x & 31;

    for (int e = i + 1 + warp; e < LSEQ; e += 8) {
        const float* p = scores + (((size_t)b * LSEQ + i) * LSEQ + e) * NC;
        float v = fmaxf(p[lane], p[lane + 32]);
        #pragma unroll
        for (int o = 16; o > 0; o >>= 1)
            v = fmaxf(v, __shfl_xor_sync(0xffffffffu, v, o));
        if (lane == 0)
            g_td[b * TRI + off1(e - i) + i] = v;
    }
}

// ---------------------------------------------------------------------------
// Kernel 2: CKY inside pass (max semiring), one CTA per batch.
// Full chart lives in SMEM in packed-diagonal layout. Thread tid owns cell
// (i=tid, e=tid+w) at each width w. Both SMEM reads are stride-1 across
// threads -> conflict-free. One __syncthreads per width.
// ---------------------------------------------------------------------------
__global__ __launch_bounds__(256, 1)
void dp_kernel(const int* __restrict__ lens, float* __restrict__ out) {
    const int b = blockIdx.x;
    extern __shared__ float D[];          // TRI floats = 130560 bytes
    const float* tb  = g_td + b * TRI;
    const int    tid = threadIdx.x;

    // Width 1: s[i, i+1] = t[i, i+1]
    for (int i = tid; i < LSEQ - 1; i += 256) D[i] = tb[i];
    __syncthreads();

    int offw   = LSEQ - 1;   // off1(2): write offset for current width
    int offwm1 = 0;          // off1(1): offset of previous diagonal

    for (int w = 2; w < LSEQ; ++w) {
        const int n = LSEQ - w;          // number of cells at this width
        float val = 0.0f;
        if (tid < n) {
            // left  child: s[i, i+j]   = D[off1(j)   + i]
            // right child: s[i+j, i+w] = D[off1(w-j) + i + j]
            float acc  = -1e30f;
            int   arow = tid;                 // off1(1) + i
            int   acol = offwm1 + tid + 1;    // off1(w-1) + i + 1
            int   drow = LSEQ - 1;            // arow stride: LSEQ - j
            int   dcol = LSEQ - w + 1;        // acol stride: -(LSEQ - w + j)
            #pragma unroll 4
            for (int j = 1; j < w; ++j) {
                acc = fmaxf(acc, D[arow] + D[acol]);
                arow += drow; --drow;
                acol -= dcol; ++dcol;
            }
            val = acc + tb[offw + tid];
        }
        // Writes target diagonal w, which no thread reads at this width, so a
        // single barrier after the writes is sufficient.
        if (tid < n) D[offw + tid] = val;
        offwm1 = offw;
        offw  += n;
        __syncthreads();
    }

    if (tid == 0) {
        int len = lens[b];
        len = len < 1 ? 1 : (len > LSEQ - 1 ? LSEQ - 1 : len);
        out[b] = D[off1(len)];            // s[0, len]
    }
}

// ---------------------------------------------------------------------------
extern "C" void kernel_launch(void* const* d_in, const int* in_sizes, int n_in,
                              void* d_out, int out_size) {
    const float* scores = (const float*)d_in[0];
    const int*   lens   = (const int*)d_in[1];
    float*       out    = (float*)d_out;
    (void)in_sizes; (void)n_in; (void)out_size;

    // Opt-in to >48KB dynamic SMEM (idempotent; host-side attribute set,
    // adds no graph nodes).
    cudaFuncSetAttribute(dp_kernel,
                         cudaFuncAttributeMaxDynamicSharedMemorySize,
                         TRI * (int)sizeof(float));

    max_kernel<<<dim3(LSEQ - 1, NB), 256>>>(scores);
    dp_kernel<<<NB, 256, TRI * sizeof(float)>>>(lens, out);
}

// round 2
// speedup vs baseline: 1.3822x; 1.3822x over previous
#include <cuda_runtime.h>
#include <cstddef>

#define LSEQ 256
#define NB   8
#define NC   64
#define TRI  (LSEQ * (LSEQ - 1) / 2)   // 32640 upper-triangle cells (w >= 1)
#define NGRP 4                          // j-range split factor

// Scratch for t = max_c scores, packed-diagonal layout per batch:
// g_td[b*TRI + off1(w) + i] = max_c scores[b, i, i+w, c]
__device__ float g_td[NB * TRI];

__host__ __device__ __forceinline__ int off1(int w) {
    return (w - 1) * LSEQ - ((w - 1) * w) / 2;
}

// ---------------------------------------------------------------------------
// Kernel 1: t[b,i,e] = max over C of scores[b,i,e,:], upper triangle only.
// ---------------------------------------------------------------------------
__global__ void max_kernel(const float* __restrict__ scores) {
    const int i    = blockIdx.x;          // 0 .. LSEQ-2
    const int b    = blockIdx.y;
    const int warp = threadIdx.x >> 5;    // 0..7
    const int lane = threadIdx.x & 31;

    for (int e = i + 1 + warp; e < LSEQ; e += 8) {
        const float* p = scores + (((size_t)b * LSEQ + i) * LSEQ + e) * NC;
        float v = fmaxf(p[lane], p[lane + 32]);
        #pragma unroll
        for (int o = 16; o > 0; o >>= 1)
            v = fmaxf(v, __shfl_xor_sync(0xffffffffu, v, o));
        if (lane == 0)
            g_td[b * TRI + off1(e - i) + i] = v;
    }
}

// ---------------------------------------------------------------------------
// Kernel 2: CKY inside pass (max semiring), one 1024-thread CTA per batch.
// Chart in SMEM, packed-diagonal layout. 4-way split of the j-range:
// thread = (g = tid>>8, c = tid&255). Each group writes a partial max to
// P[g][c]; threads < 256 combine, add the prefetched t term, and store.
// Both SMEM operands are stride-1 across lanes -> conflict-free.
// ---------------------------------------------------------------------------
__global__ __launch_bounds__(1024, 1)
void dp_kernel(const int* __restrict__ lens, float* __restrict__ out) {
    const int b = blockIdx.x;
    extern __shared__ float S[];
    float* D = S;                       // TRI floats (chart)
    float* P = S + TRI + 4;             // NGRP * 256 floats (partials)
    const float* tb  = g_td + b * TRI;
    const int    tid = threadIdx.x;
    const int    c   = tid & 255;
    const int    g   = tid >> 8;

    // Width 1: s[i, i+1] = t[i, i+1]
    for (int i = tid; i < LSEQ - 1; i += 1024) D[i] = tb[i];
    __syncthreads();

    // Prefetch t for width 2 (clamped so all of tid<256 stay in bounds).
    float tcur = 0.0f;
    if (tid < 256) tcur = tb[off1(2) + (tid < LSEQ - 3 ? tid : LSEQ - 3)];

    int offw = LSEQ - 1;                // off1(2)

    for (int w = 2; w < LSEQ; ++w) {
        const int n = LSEQ - w;         // cells at this width
        float part = -1e30f;
        if (c < n) {
            const int m   = w - 1;                 // number of split points
            const int jlo = 1 + ((g * m) >> 2);
            const int jhi = 1 + (((g + 1) * m) >> 2);
            // left  child: s[c, c+j]   = D[off1(j)   + c]
            // right child: s[c+j, c+w] = D[off1(w-j) + c + j]
            int arow = off1(jlo) + c;
            int drow = LSEQ - jlo;
            int acol = off1(w - jlo) + c + jlo;
            int dcol = LSEQ - w + jlo;
            #pragma unroll 4
            for (int j = jlo; j < jhi; ++j) {
                part = fmaxf(part, D[arow] + D[acol]);
                arow += drow; --drow;
                acol -= dcol; ++dcol;
            }
        }
        P[(g << 8) + c] = part;
        __syncthreads();

        if (tid < 256) {
            if (tid < n) {
                float v = fmaxf(fmaxf(P[tid],       P[256 + tid]),
                                fmaxf(P[512 + tid], P[768 + tid]));
                D[offw + tid] = v + tcur;
            }
            // Prefetch t for width w+1; overlapped by next width's j-loop.
            int offn = offw + n;               // off1(w+1)
            int idx  = offn + tid;
            int lim  = offn + (n - 2 >= 0 ? n - 2 : 0);   // offn + n_next - 1
            if (idx > lim) idx = lim;
            if (idx > TRI - 1) idx = TRI - 1;  // w=255: no next width
            tcur = tb[idx];
        }
        offw += n;
        __syncthreads();
    }

    if (tid == 0) {
        int len = lens[b];
        len = len < 1 ? 1 : (len > LSEQ - 1 ? LSEQ - 1 : len);
        out[b] = D[off1(len)];          // s[0, len]
    }
}

// ---------------------------------------------------------------------------
extern "C" void kernel_launch(void* const* d_in, const int* in_sizes, int n_in,
                              void* d_out, int out_size) {
    const float* scores = (const float*)d_in[0];
    const int*   lens   = (const int*)d_in[1];
    float*       out    = (float*)d_out;
    (void)in_sizes; (void)n_in; (void)out_size;

    const int smem = (TRI + 4 + NGRP * 256) * (int)sizeof(float);
    cudaFuncSetAttribute(dp_kernel,
                         cudaFuncAttributeMaxDynamicSharedMemorySize, smem);

    max_kernel<<<dim3(LSEQ - 1, NB), 256>>>(scores);
    dp_kernel<<<NB, 1024, smem>>>(lens, out);
}